// round 14
// baseline (speedup 1.0000x reference)
#include <cuda_runtime.h>
#include <cuda_fp16.h>
#include <math.h>
#include <stdint.h>

// Problem constants
#define D_MODEL 1024
#define N_HEADS 16
#define D_HEAD  64
#define SEQ     2048
#define BATCH   2
#define NTOK    (BATCH * SEQ)        // 4096
#define TRIPLE  (3 * D_MODEL)        // 3072

// Scratch (allocation-free rule: __device__ globals)
__device__ __half g_a [(size_t)NTOK * D_MODEL];    // fp16 x, then ctx
__device__ __half g_wq[(size_t)TRIPLE * D_MODEL];  // W_qkv^T fp16
__device__ __half g_wp[(size_t)D_MODEL * D_MODEL]; // W_proj^T fp16
__device__ __half g_qh[(size_t)NTOK * TRIPLE];     // qkv fp16

// ============================ helpers ========================================
__device__ __forceinline__ uint32_t smem_u32(const void* p) {
    uint32_t a;
    asm("{ .reg .u64 t; cvta.to.shared.u64 t, %1; cvt.u32.u64 %0, t; }" : "=r"(a) : "l"(p));
    return a;
}
#define SW128(off) ((off) ^ (((off) >> 3) & 0x70))

__device__ __forceinline__ void cp16(uint32_t dst, const void* src) {
    asm volatile("cp.async.cg.shared.global [%0], [%1], 16;" :: "r"(dst), "l"(src) : "memory");
}
#define CP_COMMIT() asm volatile("cp.async.commit_group;" ::: "memory")
#define CP_WAIT(n)  asm volatile("cp.async.wait_group %0;" :: "n"(n) : "memory")

__device__ __forceinline__ void ldmx4(uint32_t* r, uint32_t addr) {
    asm volatile("ldmatrix.sync.aligned.m8n8.x4.shared.b16 {%0,%1,%2,%3}, [%4];"
                 : "=r"(r[0]), "=r"(r[1]), "=r"(r[2]), "=r"(r[3]) : "r"(addr));
}
__device__ __forceinline__ void ldmx2(uint32_t* r, uint32_t addr) {
    asm volatile("ldmatrix.sync.aligned.m8n8.x2.shared.b16 {%0,%1}, [%2];"
                 : "=r"(r[0]), "=r"(r[1]) : "r"(addr));
}
__device__ __forceinline__ void ldmx4t(uint32_t* r, uint32_t addr) {
    asm volatile("ldmatrix.sync.aligned.m8n8.x4.trans.shared.b16 {%0,%1,%2,%3}, [%4];"
                 : "=r"(r[0]), "=r"(r[1]), "=r"(r[2]), "=r"(r[3]) : "r"(addr));
}
__device__ __forceinline__ void mma16816(float* d, const uint32_t* a, const uint32_t* b) {
    asm volatile(
        "mma.sync.aligned.m16n8k16.row.col.f32.f16.f16.f32 "
        "{%0,%1,%2,%3}, {%4,%5,%6,%7}, {%8,%9}, {%0,%1,%2,%3};"
        : "+f"(d[0]), "+f"(d[1]), "+f"(d[2]), "+f"(d[3])
        : "r"(a[0]), "r"(a[1]), "r"(a[2]), "r"(a[3]), "r"(b[0]), "r"(b[1]));
}
__device__ __forceinline__ uint32_t packh2(float a, float b) {
    __half2 t = __floats2half2_rn(a, b);
    return *reinterpret_cast<uint32_t*>(&t);
}
__device__ __forceinline__ uint32_t ex2h2(uint32_t x) {
    uint32_t r;
    asm("ex2.approx.f16x2 %0, %1;" : "=r"(r) : "r"(x));
    return r;
}

// ============================ conversion kernels =============================
// x f32 [M][1024] -> fp16 [M][1024]
__global__ __launch_bounds__(256) void convert_a_kernel(
    const float* __restrict__ src, __half* __restrict__ dst, int total4)
{
    int i = blockIdx.x * blockDim.x + threadIdx.x;
    if (i >= total4) return;
    float4 v = *(const float4*)&src[i * 4];
    __half2 h0 = __floats2half2_rn(v.x, v.y);
    __half2 h1 = __floats2half2_rn(v.z, v.w);
    *(__half2*)&dst[i * 4]     = h0;
    *(__half2*)&dst[i * 4 + 2] = h1;
}

// Both W conversions in one launch: z=0 -> W_qkv (N=3072), z=1 -> W_proj (N=1024)
__global__ __launch_bounds__(256) void convert_w_kernel(
    const float* __restrict__ Wq, __half* __restrict__ dq,
    const float* __restrict__ Wp, __half* __restrict__ dp)
{
    const float* W = (blockIdx.z == 0) ? Wq : Wp;
    __half* dst    = (blockIdx.z == 0) ? dq : dp;
    const int N    = (blockIdx.z == 0) ? TRIPLE : D_MODEL;
    int n0 = blockIdx.x * 32;
    if (n0 >= N) return;
    int k0 = blockIdx.y * 32;
    __shared__ float tile[32][33];
    int tx = threadIdx.x, ty = threadIdx.y;             // (32, 8)
    #pragma unroll
    for (int j = 0; j < 32; j += 8)
        tile[ty + j][tx] = W[(size_t)(k0 + ty + j) * N + n0 + tx];
    __syncthreads();
    #pragma unroll
    for (int j = 0; j < 32; j += 8) {
        int n = n0 + ty + j, k = k0 + tx;
        dst[(size_t)n * D_MODEL + k] = __float2half_rn(tile[tx][ty + j]);
    }
}

// ============================ HMMA fp16 GEMM =================================
// C[M,N] = A[M,1024] @ B[N,1024]^T + bias[N]; plain fp16 operands, fp32 acc.
#define NSTAGES 3
#define NCHUNK 16                    // 16 chunks of K=64 (128B rows)
#define STAGE_BYTES 32768            // A 16KB + B 16KB
#define GEMM_SMEM (NSTAGES * STAGE_BYTES)

template<int MODE>
__global__ __launch_bounds__(256, 2) void gemm_hmma_kernel(
    const __half* __restrict__ A, const __half* __restrict__ B,
    const float* __restrict__ bias, float* __restrict__ C,
    __half* __restrict__ Ch, int N)
{
    extern __shared__ char smem[];
    const uint32_t sb = smem_u32(smem);
    const int tid  = threadIdx.x;
    const int wid  = tid >> 5;
    const int lane = tid & 31;
    const int wm   = wid & 1;
    const int wn   = wid >> 1;
    const int m0   = blockIdx.y * 128;
    const int n0   = blockIdx.x * 128;

    float acc[4][4][4];
    #pragma unroll
    for (int i = 0; i < 4; ++i)
        #pragma unroll
        for (int j = 0; j < 4; ++j)
            #pragma unroll
            for (int r = 0; r < 4; ++r) acc[i][j][r] = 0.f;

    const __half* Ab = A + (size_t)m0 * D_MODEL;
    const __half* Bb = B + (size_t)n0 * D_MODEL;

    auto load_chunk = [&](int c) {
        int s = c % NSTAGES;
        uint32_t sa = sb + s * STAGE_BYTES;
        uint32_t sB = sa + 16384;
        size_t koff = (size_t)c * 64;
        #pragma unroll
        for (int t = 0; t < 4; ++t) {
            int id = tid + t * 256;
            int r = id >> 3, c16 = id & 7;
            uint32_t soff = SW128(r * 128 + c16 * 16);
            cp16(sa + soff, Ab + (size_t)r * D_MODEL + koff + c16 * 8);
            cp16(sB + soff, Bb + (size_t)r * D_MODEL + koff + c16 * 8);
        }
        CP_COMMIT();
    };

    const int a_row = wm * 64 + (lane & 15);
    const int a_kb  = (lane >> 4) * 16;
    const int b_row = wn * 32 + (lane & 7);
    const int b_kb  = ((lane >> 3) & 1) * 16;

    load_chunk(0);
    load_chunk(1);

    for (int c = 0; c < NCHUNK; ++c) {
        if (c == NCHUNK - 1) { CP_WAIT(0); } else { CP_WAIT(1); }
        __syncthreads();
        if (c + 2 < NCHUNK) load_chunk(c + 2);

        int s = c % NSTAGES;
        uint32_t sa = sb + s * STAGE_BYTES;
        uint32_t sB = sa + 16384;

        #pragma unroll
        for (int j = 0; j < 4; ++j) {          // 4 k16 groups per chunk
            uint32_t ahf[4][4];
            #pragma unroll
            for (int mt = 0; mt < 4; ++mt) {
                uint32_t base = (uint32_t)((a_row + mt * 16) * 128 + j * 32 + a_kb);
                ldmx4(ahf[mt], sa + SW128(base));
            }
            #pragma unroll
            for (int nt = 0; nt < 4; ++nt) {
                uint32_t bh[2];
                uint32_t base = (uint32_t)((b_row + nt * 8) * 128 + j * 32 + b_kb);
                ldmx2(bh, sB + SW128(base));
                #pragma unroll
                for (int mt = 0; mt < 4; ++mt) mma16816(acc[mt][nt], ahf[mt], bh);
            }
        }
    }

    const int er = lane >> 2;
    const int ec = (lane & 3) * 2;
    #pragma unroll
    for (int mt = 0; mt < 4; ++mt) {
        #pragma unroll
        for (int nt = 0; nt < 4; ++nt) {
            int col = n0 + wn * 32 + nt * 8 + ec;
            float bx = bias[col], by = bias[col + 1];
            size_t r0 = (size_t)(m0 + wm * 64 + mt * 16 + er);
            float v00 = acc[mt][nt][0] + bx, v01 = acc[mt][nt][1] + by;
            float v10 = acc[mt][nt][2] + bx, v11 = acc[mt][nt][3] + by;
            if (MODE == 0) {
                float2 a0 = { v00, v01 }, a1 = { v10, v11 };
                *(float2*)&C[r0 * N + col]       = a0;
                *(float2*)&C[(r0 + 8) * N + col] = a1;
            } else {
                __half2 h0 = __floats2half2_rn(v00, v01);
                __half2 h1 = __floats2half2_rn(v10, v11);
                *(__half2*)&Ch[r0 * N + col]       = h0;
                *(__half2*)&Ch[(r0 + 8) * N + col] = h1;
            }
        }
    }
}

// ============================ HMMA flash attention v6 ========================
// 8 warps x 16 Q rows, x4 ldmatrix. No online max. S in log2 domain,
// P = ex2.approx.f16x2. l via ones-MMA. S k-reduction split into two
// independent accumulator chains (ks 0-1 and ks 2-3) to double MMA-level
// parallelism in the latency-critical S phase.
#define ABQ 128
#define ABK 64
#define ATTN_SMEM (16384 + 2 * 16384)   // Q 16KB | 2 stages x (K 8KB, V 8KB)

__global__ __launch_bounds__(256, 2) void attn_hmma_kernel(
    const __half* __restrict__ qkv, __half* __restrict__ ctxA)
{
    extern __shared__ char smem[];
    const uint32_t sb = smem_u32(smem);
    const uint32_t QH = 0, STG = 16384;

    const int tid = threadIdx.x, wid = tid >> 5, lane = tid & 31;
    const int qt = (int)gridDim.x - 1 - (int)blockIdx.x;   // big tiles first
    const int h = blockIdx.y, b = blockIdx.z;
    const int q0 = qt * ABQ;
    const size_t rowbase = (size_t)b * SEQ;
    const int qcol = h * 64, kcol = 1024 + h * 64, vcol = 2048 + h * 64;

    // Q tile: 128 rows x 64 fp16 (1024 cp16, 4 per thread)
    #pragma unroll
    for (int t = 0; t < 4; ++t) {
        int id = tid + t * 256;
        int r = id >> 3, c = id & 7;
        uint32_t so = SW128(r * 128 + c * 16);
        cp16(sb + QH + so, qkv + (rowbase + q0 + r) * TRIPLE + qcol + c * 8);
    }
    CP_COMMIT();

    const int T = (q0 + ABQ) / ABK;

    auto load_kv = [&](int t) {
        uint32_t st = sb + STG + (uint32_t)(t & 1) * 16384;
        int k0 = t * ABK;
        #pragma unroll
        for (int i = 0; i < 2; ++i) {
            int id = tid + i * 256;              // 0..511
            int r = id >> 3, c = id & 7;         // r 0..63
            uint32_t so = SW128(r * 128 + c * 16);
            size_t grow = (rowbase + k0 + r) * TRIPLE;
            cp16(st + 0    + so, qkv + grow + kcol + c * 8);
            cp16(st + 8192 + so, qkv + grow + vcol + c * 8);
        }
        CP_COMMIT();
    };
    load_kv(0);
    CP_WAIT(0);
    __syncthreads();

    // persistent Q fragments: 16 rows x 64 dims, pre-scaled by log2(e)/8
    uint32_t qhf[4][4];
    {
        int arow = wid * 16 + (lane & 15);
        int akb = (lane >> 4) * 16;
        const __half2 sc = __floats2half2_rn(0.180336878f, 0.180336878f); // log2e/8
        #pragma unroll
        for (int ks = 0; ks < 4; ++ks) {
            ldmx4(qhf[ks], sb + QH + SW128((uint32_t)(arow * 128 + ks * 32 + akb)));
            #pragma unroll
            for (int r = 0; r < 4; ++r) {
                __half2 v = *reinterpret_cast<__half2*>(&qhf[ks][r]);
                v = __hmul2(v, sc);
                qhf[ks][r] = *reinterpret_cast<uint32_t*>(&v);
            }
        }
    }

    float l_acc[4] = {0.f, 0.f, 0.f, 0.f};       // ones-MMA accumulator
    float o_acc[8][4];
    #pragma unroll
    for (int nt = 0; nt < 8; ++nt)
        #pragma unroll
        for (int r = 0; r < 4; ++r) o_acc[nt][r] = 0.f;

    const uint32_t ones2 = packh2(1.0f, 1.0f);
    uint32_t bones[2] = { ones2, ones2 };

    const int r0l = lane >> 2;
    const int ecol = (lane & 3) * 2;
    const int wrow_lo = q0 + wid * 16;          // warp's min Q row
    const int wrow_hi = wrow_lo + 15;           // warp's max Q row
    const int qr0 = wrow_lo + r0l;
    const int qr1 = qr0 + 8;

    // K x4 address: lanes 0-15 -> column group np*2, lanes 16-31 -> np*2+1
    const int k_row8 = lane & 7;
    const int k_qsel = lane >> 4;
    const int k_khalf = (lane >> 3) & 1;
    // V x4t address: lanes 0-15 -> nt group, lanes 16-31 -> nt+1 group
    const int v_row = lane & 15;
    const int v_nsel = lane >> 4;

    for (int t = 0; t < T; ++t) {
        __syncthreads();
        if (t + 1 < T) { load_kv(t + 1); CP_WAIT(1); } else { CP_WAIT(0); }
        __syncthreads();

        const int kb0 = t * ABK;
        if (kb0 > wrow_hi) continue;             // fully masked for this warp

        uint32_t st = sb + STG + (uint32_t)(t & 1) * 16384;
        const bool need_mask = (kb0 + 63 > wrow_lo);

        #pragma unroll
        for (int np = 0; np < 4; ++np) {         // 16-KV-column group
            // ---- S (log2 domain): two independent k-half chains ----
            float sA[2][4], sB[2][4];
            #pragma unroll
            for (int q = 0; q < 2; ++q)
                #pragma unroll
                for (int r = 0; r < 4; ++r) { sA[q][r] = 0.f; sB[q][r] = 0.f; }

            #pragma unroll
            for (int ks = 0; ks < 2; ++ks) {
                uint32_t kf[4];
                uint32_t off = (uint32_t)(((np * 2 + k_qsel) * 8 + k_row8) * 128
                                          + ks * 32 + k_khalf * 16);
                ldmx4(kf, st + 0 + SW128(off));
                mma16816(sA[0], qhf[ks], kf + 0);
                mma16816(sA[1], qhf[ks], kf + 2);
            }
            #pragma unroll
            for (int ks = 2; ks < 4; ++ks) {
                uint32_t kf[4];
                uint32_t off = (uint32_t)(((np * 2 + k_qsel) * 8 + k_row8) * 128
                                          + ks * 32 + k_khalf * 16);
                ldmx4(kf, st + 0 + SW128(off));
                mma16816(sB[0], qhf[ks], kf + 0);
                mma16816(sB[1], qhf[ks], kf + 2);
            }

            float s[2][4];
            #pragma unroll
            for (int q = 0; q < 2; ++q)
                #pragma unroll
                for (int r = 0; r < 4; ++r) s[q][r] = sA[q][r] + sB[q][r];

            // ---- mask (cvt -> -inf -> ex2 -> 0) ----
            if (need_mask) {
                #pragma unroll
                for (int q = 0; q < 2; ++q) {
                    int kc = kb0 + (np * 2 + q) * 8 + ecol;
                    if (kc     > qr0) s[q][0] = -1e30f;
                    if (kc + 1 > qr0) s[q][1] = -1e30f;
                    if (kc     > qr1) s[q][2] = -1e30f;
                    if (kc + 1 > qr1) s[q][3] = -1e30f;
                }
            }

            // ---- P = ex2(S) in fp16x2, fragment layout ----
            uint32_t pha[4];
            pha[0] = ex2h2(packh2(s[0][0], s[0][1]));
            pha[1] = ex2h2(packh2(s[0][2], s[0][3]));
            pha[2] = ex2h2(packh2(s[1][0], s[1][1]));
            pha[3] = ex2h2(packh2(s[1][2], s[1][3]));

            // ---- O += P[np] V[np]; l += P @ ones interleaved ----
            #pragma unroll
            for (int nt2 = 0; nt2 < 4; ++nt2) {
                uint32_t vf[4];
                uint32_t off = (uint32_t)((np * 16 + v_row) * 128
                                          + (nt2 * 2 + v_nsel) * 16);
                ldmx4t(vf, st + 8192 + SW128(off));
                mma16816(o_acc[nt2 * 2 + 0], pha, vf + 0);
                mma16816(o_acc[nt2 * 2 + 1], pha, vf + 2);
                if (nt2 == 0) mma16816(l_acc, pha, bones);
            }
        }
    }

    // ---- normalize + store (l already reduced by the ones-MMA) ----
    float inv0 = 1.0f / l_acc[0], inv1 = 1.0f / l_acc[2];
    size_t tok0 = rowbase + (size_t)q0 + wid * 16 + r0l;
    #pragma unroll
    for (int nt = 0; nt < 8; ++nt) {
        int gcol = h * 64 + nt * 8 + ecol;
        *(__half2*)&ctxA[tok0 * D_MODEL + gcol] =
            __floats2half2_rn(o_acc[nt][0] * inv0, o_acc[nt][1] * inv0);
        *(__half2*)&ctxA[(tok0 + 8) * D_MODEL + gcol] =
            __floats2half2_rn(o_acc[nt][2] * inv1, o_acc[nt][3] * inv1);
    }
}

// ============================ launch =========================================
extern "C" void kernel_launch(void* const* d_in, const int* in_sizes, int n_in,
                              void* d_out, int out_size)
{
    (void)in_sizes; (void)n_in; (void)out_size;
    const float* x      = (const float*)d_in[0];
    const float* W_qkv  = (const float*)d_in[1];
    const float* b_qkv  = (const float*)d_in[2];
    const float* W_proj = (const float*)d_in[3];
    const float* b_proj = (const float*)d_in[4];
    float* out = (float*)d_out;

    __half *a_buf, *wq_buf, *wp_buf, *qh_buf;
    cudaGetSymbolAddress((void**)&a_buf, g_a);
    cudaGetSymbolAddress((void**)&wq_buf, g_wq);
    cudaGetSymbolAddress((void**)&wp_buf, g_wp);
    cudaGetSymbolAddress((void**)&qh_buf, g_qh);

    static bool attr_set = false;
    if (!attr_set) {
        cudaFuncSetAttribute(gemm_hmma_kernel<0>, cudaFuncAttributeMaxDynamicSharedMemorySize, GEMM_SMEM);
        cudaFuncSetAttribute(gemm_hmma_kernel<1>, cudaFuncAttributeMaxDynamicSharedMemorySize, GEMM_SMEM);
        cudaFuncSetAttribute(attn_hmma_kernel, cudaFuncAttributeMaxDynamicSharedMemorySize, ATTN_SMEM);
        attr_set = true;
    }

    // 1) conversions to fp16 (both W's in one launch)
    convert_a_kernel<<<(NTOK * D_MODEL / 4 + 255) / 256, 256>>>(x, a_buf, NTOK * D_MODEL / 4);
    {
        dim3 grid(TRIPLE / 32, D_MODEL / 32, 2);
        convert_w_kernel<<<grid, dim3(32, 8)>>>(W_qkv, wq_buf, W_proj, wp_buf);
    }

    // 2) QKV GEMM -> fp16 qkv
    {
        dim3 grid(TRIPLE / 128, NTOK / 128);
        gemm_hmma_kernel<1><<<grid, 256, GEMM_SMEM>>>(a_buf, wq_buf, b_qkv, nullptr, qh_buf, TRIPLE);
    }

    // 3) HMMA flash attention v6 -> ctx fp16 (overwrites g_a)
    {
        dim3 grid(SEQ / ABQ, N_HEADS, BATCH);
        attn_hmma_kernel<<<grid, 256, ATTN_SMEM>>>(qh_buf, a_buf);
    }

    // 4) output projection (fp32 out + bias)
    {
        dim3 grid(D_MODEL / 128, NTOK / 128);
        gemm_hmma_kernel<0><<<grid, 256, GEMM_SMEM>>>(a_buf, wp_buf, b_proj, out, nullptr, D_MODEL);
    }
}

// round 15
// speedup vs baseline: 1.0094x; 1.0094x over previous
#include <cuda_runtime.h>
#include <cuda_fp16.h>
#include <math.h>
#include <stdint.h>

// Problem constants
#define D_MODEL 1024
#define N_HEADS 16
#define D_HEAD  64
#define SEQ     2048
#define BATCH   2
#define NTOK    (BATCH * SEQ)        // 4096
#define TRIPLE  (3 * D_MODEL)        // 3072

// Scratch (allocation-free rule: __device__ globals)
__device__ __half g_a [(size_t)NTOK * D_MODEL];    // fp16 x, then ctx
__device__ __half g_wq[(size_t)TRIPLE * D_MODEL];  // W_qkv^T fp16
__device__ __half g_wp[(size_t)D_MODEL * D_MODEL]; // W_proj^T fp16
__device__ __half g_qh[(size_t)NTOK * TRIPLE];     // qkv fp16

// ============================ helpers ========================================
__device__ __forceinline__ uint32_t smem_u32(const void* p) {
    uint32_t a;
    asm("{ .reg .u64 t; cvta.to.shared.u64 t, %1; cvt.u32.u64 %0, t; }" : "=r"(a) : "l"(p));
    return a;
}
#define SW128(off) ((off) ^ (((off) >> 3) & 0x70))

__device__ __forceinline__ void cp16(uint32_t dst, const void* src) {
    asm volatile("cp.async.cg.shared.global [%0], [%1], 16;" :: "r"(dst), "l"(src) : "memory");
}
#define CP_COMMIT() asm volatile("cp.async.commit_group;" ::: "memory")
#define CP_WAIT(n)  asm volatile("cp.async.wait_group %0;" :: "n"(n) : "memory")

__device__ __forceinline__ void ldmx4(uint32_t* r, uint32_t addr) {
    asm volatile("ldmatrix.sync.aligned.m8n8.x4.shared.b16 {%0,%1,%2,%3}, [%4];"
                 : "=r"(r[0]), "=r"(r[1]), "=r"(r[2]), "=r"(r[3]) : "r"(addr));
}
__device__ __forceinline__ void ldmx2(uint32_t* r, uint32_t addr) {
    asm volatile("ldmatrix.sync.aligned.m8n8.x2.shared.b16 {%0,%1}, [%2];"
                 : "=r"(r[0]), "=r"(r[1]) : "r"(addr));
}
__device__ __forceinline__ void ldmx4t(uint32_t* r, uint32_t addr) {
    asm volatile("ldmatrix.sync.aligned.m8n8.x4.trans.shared.b16 {%0,%1,%2,%3}, [%4];"
                 : "=r"(r[0]), "=r"(r[1]), "=r"(r[2]), "=r"(r[3]) : "r"(addr));
}
__device__ __forceinline__ void mma16816(float* d, const uint32_t* a, const uint32_t* b) {
    asm volatile(
        "mma.sync.aligned.m16n8k16.row.col.f32.f16.f16.f32 "
        "{%0,%1,%2,%3}, {%4,%5,%6,%7}, {%8,%9}, {%0,%1,%2,%3};"
        : "+f"(d[0]), "+f"(d[1]), "+f"(d[2]), "+f"(d[3])
        : "r"(a[0]), "r"(a[1]), "r"(a[2]), "r"(a[3]), "r"(b[0]), "r"(b[1]));
}
__device__ __forceinline__ uint32_t packh2(float a, float b) {
    __half2 t = __floats2half2_rn(a, b);
    return *reinterpret_cast<uint32_t*>(&t);
}
__device__ __forceinline__ uint32_t ex2h2(uint32_t x) {
    uint32_t r;
    asm("ex2.approx.f16x2 %0, %1;" : "=r"(r) : "r"(x));
    return r;
}

// ============================ conversion kernels =============================
// x f32 [M][1024] -> fp16 [M][1024]
__global__ __launch_bounds__(256) void convert_a_kernel(
    const float* __restrict__ src, __half* __restrict__ dst, int total4)
{
    int i = blockIdx.x * blockDim.x + threadIdx.x;
    if (i >= total4) return;
    float4 v = *(const float4*)&src[i * 4];
    __half2 h0 = __floats2half2_rn(v.x, v.y);
    __half2 h1 = __floats2half2_rn(v.z, v.w);
    *(__half2*)&dst[i * 4]     = h0;
    *(__half2*)&dst[i * 4 + 2] = h1;
}

// Both W conversions in one launch: z=0 -> W_qkv (N=3072), z=1 -> W_proj (N=1024)
__global__ __launch_bounds__(256) void convert_w_kernel(
    const float* __restrict__ Wq, __half* __restrict__ dq,
    const float* __restrict__ Wp, __half* __restrict__ dp)
{
    const float* W = (blockIdx.z == 0) ? Wq : Wp;
    __half* dst    = (blockIdx.z == 0) ? dq : dp;
    const int N    = (blockIdx.z == 0) ? TRIPLE : D_MODEL;
    int n0 = blockIdx.x * 32;
    if (n0 >= N) return;
    int k0 = blockIdx.y * 32;
    __shared__ float tile[32][33];
    int tx = threadIdx.x, ty = threadIdx.y;             // (32, 8)
    #pragma unroll
    for (int j = 0; j < 32; j += 8)
        tile[ty + j][tx] = W[(size_t)(k0 + ty + j) * N + n0 + tx];
    __syncthreads();
    #pragma unroll
    for (int j = 0; j < 32; j += 8) {
        int n = n0 + ty + j, k = k0 + tx;
        dst[(size_t)n * D_MODEL + k] = __float2half_rn(tile[tx][ty + j]);
    }
}

// ============================ HMMA fp16 GEMM =================================
// C[M,N] = A[M,1024] @ B[N,1024]^T + bias[N]; plain fp16 operands, fp32 acc.
#define NSTAGES 3
#define NCHUNK 16                    // 16 chunks of K=64 (128B rows)
#define STAGE_BYTES 32768            // A 16KB + B 16KB
#define GEMM_SMEM (NSTAGES * STAGE_BYTES)

template<int MODE>
__global__ __launch_bounds__(256, 2) void gemm_hmma_kernel(
    const __half* __restrict__ A, const __half* __restrict__ B,
    const float* __restrict__ bias, float* __restrict__ C,
    __half* __restrict__ Ch, int N)
{
    extern __shared__ char smem[];
    const uint32_t sb = smem_u32(smem);
    const int tid  = threadIdx.x;
    const int wid  = tid >> 5;
    const int lane = tid & 31;
    const int wm   = wid & 1;
    const int wn   = wid >> 1;
    const int m0   = blockIdx.y * 128;
    const int n0   = blockIdx.x * 128;

    float acc[4][4][4];
    #pragma unroll
    for (int i = 0; i < 4; ++i)
        #pragma unroll
        for (int j = 0; j < 4; ++j)
            #pragma unroll
            for (int r = 0; r < 4; ++r) acc[i][j][r] = 0.f;

    const __half* Ab = A + (size_t)m0 * D_MODEL;
    const __half* Bb = B + (size_t)n0 * D_MODEL;

    auto load_chunk = [&](int c) {
        int s = c % NSTAGES;
        uint32_t sa = sb + s * STAGE_BYTES;
        uint32_t sB = sa + 16384;
        size_t koff = (size_t)c * 64;
        #pragma unroll
        for (int t = 0; t < 4; ++t) {
            int id = tid + t * 256;
            int r = id >> 3, c16 = id & 7;
            uint32_t soff = SW128(r * 128 + c16 * 16);
            cp16(sa + soff, Ab + (size_t)r * D_MODEL + koff + c16 * 8);
            cp16(sB + soff, Bb + (size_t)r * D_MODEL + koff + c16 * 8);
        }
        CP_COMMIT();
    };

    const int a_row = wm * 64 + (lane & 15);
    const int a_kb  = (lane >> 4) * 16;
    const int b_row = wn * 32 + (lane & 7);
    const int b_kb  = ((lane >> 3) & 1) * 16;

    load_chunk(0);
    load_chunk(1);

    for (int c = 0; c < NCHUNK; ++c) {
        if (c == NCHUNK - 1) { CP_WAIT(0); } else { CP_WAIT(1); }
        __syncthreads();
        if (c + 2 < NCHUNK) load_chunk(c + 2);

        int s = c % NSTAGES;
        uint32_t sa = sb + s * STAGE_BYTES;
        uint32_t sB = sa + 16384;

        #pragma unroll
        for (int j = 0; j < 4; ++j) {          // 4 k16 groups per chunk
            uint32_t ahf[4][4];
            #pragma unroll
            for (int mt = 0; mt < 4; ++mt) {
                uint32_t base = (uint32_t)((a_row + mt * 16) * 128 + j * 32 + a_kb);
                ldmx4(ahf[mt], sa + SW128(base));
            }
            #pragma unroll
            for (int nt = 0; nt < 4; ++nt) {
                uint32_t bh[2];
                uint32_t base = (uint32_t)((b_row + nt * 8) * 128 + j * 32 + b_kb);
                ldmx2(bh, sB + SW128(base));
                #pragma unroll
                for (int mt = 0; mt < 4; ++mt) mma16816(acc[mt][nt], ahf[mt], bh);
            }
        }
    }

    const int er = lane >> 2;
    const int ec = (lane & 3) * 2;
    #pragma unroll
    for (int mt = 0; mt < 4; ++mt) {
        #pragma unroll
        for (int nt = 0; nt < 4; ++nt) {
            int col = n0 + wn * 32 + nt * 8 + ec;
            float bx = bias[col], by = bias[col + 1];
            size_t r0 = (size_t)(m0 + wm * 64 + mt * 16 + er);
            float v00 = acc[mt][nt][0] + bx, v01 = acc[mt][nt][1] + by;
            float v10 = acc[mt][nt][2] + bx, v11 = acc[mt][nt][3] + by;
            if (MODE == 0) {
                float2 a0 = { v00, v01 }, a1 = { v10, v11 };
                *(float2*)&C[r0 * N + col]       = a0;
                *(float2*)&C[(r0 + 8) * N + col] = a1;
            } else {
                __half2 h0 = __floats2half2_rn(v00, v01);
                __half2 h1 = __floats2half2_rn(v10, v11);
                *(__half2*)&Ch[r0 * N + col]       = h0;
                *(__half2*)&Ch[(r0 + 8) * N + col] = h1;
            }
        }
    }
}

// ============================ HMMA flash attention v7 ========================
// 8 warps x 16 Q rows, x4 ldmatrix. No online max. S in log2 domain,
// P = ex2.approx.f16x2, l via ones-MMA (R13 arithmetic, unchanged).
// Software pipeline: S-MMAs of group np+1 are interleaved with O-MMAs of
// group np (data-independent), hiding the S chain behind the O phase.
#define ABQ 128
#define ABK 64
#define ATTN_SMEM (16384 + 2 * 16384)   // Q 16KB | 2 stages x (K 8KB, V 8KB)

__global__ __launch_bounds__(256, 2) void attn_hmma_kernel(
    const __half* __restrict__ qkv, __half* __restrict__ ctxA)
{
    extern __shared__ char smem[];
    const uint32_t sb = smem_u32(smem);
    const uint32_t QH = 0, STG = 16384;

    const int tid = threadIdx.x, wid = tid >> 5, lane = tid & 31;
    const int qt = (int)gridDim.x - 1 - (int)blockIdx.x;   // big tiles first
    const int h = blockIdx.y, b = blockIdx.z;
    const int q0 = qt * ABQ;
    const size_t rowbase = (size_t)b * SEQ;
    const int qcol = h * 64, kcol = 1024 + h * 64, vcol = 2048 + h * 64;

    // Q tile: 128 rows x 64 fp16 (1024 cp16, 4 per thread)
    #pragma unroll
    for (int t = 0; t < 4; ++t) {
        int id = tid + t * 256;
        int r = id >> 3, c = id & 7;
        uint32_t so = SW128(r * 128 + c * 16);
        cp16(sb + QH + so, qkv + (rowbase + q0 + r) * TRIPLE + qcol + c * 8);
    }
    CP_COMMIT();

    const int T = (q0 + ABQ) / ABK;

    auto load_kv = [&](int t) {
        uint32_t st = sb + STG + (uint32_t)(t & 1) * 16384;
        int k0 = t * ABK;
        #pragma unroll
        for (int i = 0; i < 2; ++i) {
            int id = tid + i * 256;              // 0..511
            int r = id >> 3, c = id & 7;         // r 0..63
            uint32_t so = SW128(r * 128 + c * 16);
            size_t grow = (rowbase + k0 + r) * TRIPLE;
            cp16(st + 0    + so, qkv + grow + kcol + c * 8);
            cp16(st + 8192 + so, qkv + grow + vcol + c * 8);
        }
        CP_COMMIT();
    };
    load_kv(0);
    CP_WAIT(0);
    __syncthreads();

    // persistent Q fragments: 16 rows x 64 dims, pre-scaled by log2(e)/8
    uint32_t qhf[4][4];
    {
        int arow = wid * 16 + (lane & 15);
        int akb = (lane >> 4) * 16;
        const __half2 sc = __floats2half2_rn(0.180336878f, 0.180336878f); // log2e/8
        #pragma unroll
        for (int ks = 0; ks < 4; ++ks) {
            ldmx4(qhf[ks], sb + QH + SW128((uint32_t)(arow * 128 + ks * 32 + akb)));
            #pragma unroll
            for (int r = 0; r < 4; ++r) {
                __half2 v = *reinterpret_cast<__half2*>(&qhf[ks][r]);
                v = __hmul2(v, sc);
                qhf[ks][r] = *reinterpret_cast<uint32_t*>(&v);
            }
        }
    }

    float l_acc[4] = {0.f, 0.f, 0.f, 0.f};       // ones-MMA accumulator
    float o_acc[8][4];
    #pragma unroll
    for (int nt = 0; nt < 8; ++nt)
        #pragma unroll
        for (int r = 0; r < 4; ++r) o_acc[nt][r] = 0.f;

    const uint32_t ones2 = packh2(1.0f, 1.0f);
    uint32_t bones[2] = { ones2, ones2 };

    const int r0l = lane >> 2;
    const int ecol = (lane & 3) * 2;
    const int wrow_lo = q0 + wid * 16;          // warp's min Q row
    const int wrow_hi = wrow_lo + 15;           // warp's max Q row
    const int qr0 = wrow_lo + r0l;
    const int qr1 = qr0 + 8;

    // K x4 address: lanes 0-15 -> column group np*2, lanes 16-31 -> np*2+1
    const int k_row8 = lane & 7;
    const int k_qsel = lane >> 4;
    const int k_khalf = (lane >> 3) & 1;
    // V x4t address: lanes 0-15 -> nt group, lanes 16-31 -> nt+1 group
    const int v_row = lane & 15;
    const int v_nsel = lane >> 4;

    for (int t = 0; t < T; ++t) {
        __syncthreads();
        if (t + 1 < T) { load_kv(t + 1); CP_WAIT(1); } else { CP_WAIT(0); }
        __syncthreads();

        const int kb0 = t * ABK;
        if (kb0 > wrow_hi) continue;             // fully masked for this warp

        uint32_t st = sb + STG + (uint32_t)(t & 1) * 16384;
        const bool need_mask = (kb0 + 63 > wrow_lo);

        // ---- prologue: S (log2 domain) for np = 0 ----
        float s_cur[2][4];
        #pragma unroll
        for (int q = 0; q < 2; ++q)
            #pragma unroll
            for (int r = 0; r < 4; ++r) s_cur[q][r] = 0.f;
        #pragma unroll
        for (int ks = 0; ks < 4; ++ks) {
            uint32_t kf[4];
            uint32_t off = (uint32_t)((k_qsel * 8 + k_row8) * 128 + ks * 32 + k_khalf * 16);
            ldmx4(kf, st + 0 + SW128(off));
            mma16816(s_cur[0], qhf[ks], kf + 0);
            mma16816(s_cur[1], qhf[ks], kf + 2);
        }

        #pragma unroll
        for (int np = 0; np < 4; ++np) {         // 16-KV-column group
            // ---- mask (cvt -> -inf -> ex2 -> 0) ----
            if (need_mask) {
                #pragma unroll
                for (int q = 0; q < 2; ++q) {
                    int kc = kb0 + (np * 2 + q) * 8 + ecol;
                    if (kc     > qr0) s_cur[q][0] = -1e30f;
                    if (kc + 1 > qr0) s_cur[q][1] = -1e30f;
                    if (kc     > qr1) s_cur[q][2] = -1e30f;
                    if (kc + 1 > qr1) s_cur[q][3] = -1e30f;
                }
            }

            // ---- P = ex2(S) in fp16x2, fragment layout ----
            uint32_t pha[4];
            pha[0] = ex2h2(packh2(s_cur[0][0], s_cur[0][1]));
            pha[1] = ex2h2(packh2(s_cur[0][2], s_cur[0][3]));
            pha[2] = ex2h2(packh2(s_cur[1][0], s_cur[1][1]));
            pha[3] = ex2h2(packh2(s_cur[1][2], s_cur[1][3]));

            // ---- O += P[np] V[np]  interleaved with  S for np+1 ----
            float s_nxt[2][4];
            #pragma unroll
            for (int q = 0; q < 2; ++q)
                #pragma unroll
                for (int r = 0; r < 4; ++r) s_nxt[q][r] = 0.f;

            #pragma unroll
            for (int i = 0; i < 4; ++i) {
                uint32_t vf[4];
                uint32_t voff = (uint32_t)((np * 16 + v_row) * 128
                                           + (i * 2 + v_nsel) * 16);
                ldmx4t(vf, st + 8192 + SW128(voff));
                mma16816(o_acc[i * 2 + 0], pha, vf + 0);
                mma16816(o_acc[i * 2 + 1], pha, vf + 2);
                if (np < 3) {
                    uint32_t kf[4];
                    uint32_t koff = (uint32_t)((((np + 1) * 2 + k_qsel) * 8 + k_row8) * 128
                                               + i * 32 + k_khalf * 16);
                    ldmx4(kf, st + 0 + SW128(koff));
                    mma16816(s_nxt[0], qhf[i], kf + 0);
                    mma16816(s_nxt[1], qhf[i], kf + 2);
                }
                if (i == 0) mma16816(l_acc, pha, bones);
            }

            #pragma unroll
            for (int q = 0; q < 2; ++q)
                #pragma unroll
                for (int r = 0; r < 4; ++r) s_cur[q][r] = s_nxt[q][r];
        }
    }

    // ---- normalize + store (l already reduced by the ones-MMA) ----
    float inv0 = 1.0f / l_acc[0], inv1 = 1.0f / l_acc[2];
    size_t tok0 = rowbase + (size_t)q0 + wid * 16 + r0l;
    #pragma unroll
    for (int nt = 0; nt < 8; ++nt) {
        int gcol = h * 64 + nt * 8 + ecol;
        *(__half2*)&ctxA[tok0 * D_MODEL + gcol] =
            __floats2half2_rn(o_acc[nt][0] * inv0, o_acc[nt][1] * inv0);
        *(__half2*)&ctxA[(tok0 + 8) * D_MODEL + gcol] =
            __floats2half2_rn(o_acc[nt][2] * inv1, o_acc[nt][3] * inv1);
    }
}

// ============================ launch =========================================
extern "C" void kernel_launch(void* const* d_in, const int* in_sizes, int n_in,
                              void* d_out, int out_size)
{
    (void)in_sizes; (void)n_in; (void)out_size;
    const float* x      = (const float*)d_in[0];
    const float* W_qkv  = (const float*)d_in[1];
    const float* b_qkv  = (const float*)d_in[2];
    const float* W_proj = (const float*)d_in[3];
    const float* b_proj = (const float*)d_in[4];
    float* out = (float*)d_out;

    __half *a_buf, *wq_buf, *wp_buf, *qh_buf;
    cudaGetSymbolAddress((void**)&a_buf, g_a);
    cudaGetSymbolAddress((void**)&wq_buf, g_wq);
    cudaGetSymbolAddress((void**)&wp_buf, g_wp);
    cudaGetSymbolAddress((void**)&qh_buf, g_qh);

    static bool attr_set = false;
    if (!attr_set) {
        cudaFuncSetAttribute(gemm_hmma_kernel<0>, cudaFuncAttributeMaxDynamicSharedMemorySize, GEMM_SMEM);
        cudaFuncSetAttribute(gemm_hmma_kernel<1>, cudaFuncAttributeMaxDynamicSharedMemorySize, GEMM_SMEM);
        cudaFuncSetAttribute(attn_hmma_kernel, cudaFuncAttributeMaxDynamicSharedMemorySize, ATTN_SMEM);
        attr_set = true;
    }

    // 1) conversions to fp16 (both W's in one launch)
    convert_a_kernel<<<(NTOK * D_MODEL / 4 + 255) / 256, 256>>>(x, a_buf, NTOK * D_MODEL / 4);
    {
        dim3 grid(TRIPLE / 32, D_MODEL / 32, 2);
        convert_w_kernel<<<grid, dim3(32, 8)>>>(W_qkv, wq_buf, W_proj, wp_buf);
    }

    // 2) QKV GEMM -> fp16 qkv
    {
        dim3 grid(TRIPLE / 128, NTOK / 128);
        gemm_hmma_kernel<1><<<grid, 256, GEMM_SMEM>>>(a_buf, wq_buf, b_qkv, nullptr, qh_buf, TRIPLE);
    }

    // 3) HMMA flash attention v7 -> ctx fp16 (overwrites g_a)
    {
        dim3 grid(SEQ / ABQ, N_HEADS, BATCH);
        attn_hmma_kernel<<<grid, 256, ATTN_SMEM>>>(qh_buf, a_buf);
    }

    // 4) output projection (fp32 out + bias)
    {
        dim3 grid(D_MODEL / 128, NTOK / 128);
        gemm_hmma_kernel<0><<<grid, 256, GEMM_SMEM>>>(a_buf, wp_buf, b_proj, out, nullptr, D_MODEL);
    }
}